// round 1
// baseline (speedup 1.0000x reference)
#include <cuda_runtime.h>

#define SEQ_LEN 131072
#define IN 100
#define HID 40

// Scratch: device globals (no allocations allowed)
__device__ float g_xs[SEQ_LEN * HID];   // input projections
__device__ float g_h[SEQ_LEN * HID];    // hidden states per step

// ---------------------------------------------------------------------------
// Kernel 1: xs[t] = Wx @ s[t] + Wx_b   (parallel over t)
// block = 320 threads = 8 timesteps x 40 outputs
// ---------------------------------------------------------------------------
__global__ void k_xproj(const float* __restrict__ s,
                        const float* __restrict__ Wx,
                        const float* __restrict__ Wxb) {
    __shared__ float sWx[HID][IN + 1];   // pad to kill bank conflicts
    __shared__ float sb[HID];
    for (int i = threadIdx.x; i < HID * IN; i += blockDim.x)
        sWx[i / IN][i % IN] = Wx[i];
    if (threadIdx.x < HID) sb[threadIdx.x] = Wxb[threadIdx.x];
    __syncthreads();

    int lt = threadIdx.x / HID;          // 0..7
    int j  = threadIdx.x % HID;
    int t  = blockIdx.x * 8 + lt;
    if (t >= SEQ_LEN) return;

    const float4* s4 = reinterpret_cast<const float4*>(s + t * IN);
    float acc = sb[j];
#pragma unroll
    for (int q = 0; q < IN / 4; q++) {
        float4 v = s4[q];
        acc += v.x * sWx[j][4 * q + 0];
        acc += v.y * sWx[j][4 * q + 1];
        acc += v.z * sWx[j][4 * q + 2];
        acc += v.w * sWx[j][4 * q + 3];
    }
    g_xs[t * HID + j] = acc;
}

// ---------------------------------------------------------------------------
// Kernel 2: sequential recurrence h_{t+1} = tanh(xs[t] + Wh h_t + b)
// 1 block, 40 threads. Wh row in registers; h ping-pong in shared;
// one barrier per step; xs prefetched 2 steps ahead (L2-resident).
// ---------------------------------------------------------------------------
__global__ void k_recur(const float* __restrict__ Wh,
                        const float* __restrict__ Whb,
                        const float* __restrict__ h0,
                        float* __restrict__ hfinal) {
    int j = threadIdx.x;                  // 0..39
    __shared__ __align__(16) float hs[2][HID];

    float w[HID];
#pragma unroll
    for (int k = 0; k < HID; k++) w[k] = Wh[j * HID + k];
    float b = Whb[j];

    hs[0][j] = h0[j];
    __syncthreads();

    float x0 = g_xs[j];                   // xs[0][j]
    float x1 = g_xs[HID + j];             // xs[1][j]

    for (int t = 0; t < SEQ_LEN; t++) {
        const float* hc = hs[t & 1];
        float a0 = 0.f, a1 = 0.f, a2 = 0.f, a3 = 0.f;
#pragma unroll
        for (int q = 0; q < HID / 4; q++) {
            float4 hv = reinterpret_cast<const float4*>(hc)[q];
            a0 += w[4 * q + 0] * hv.x;
            a1 += w[4 * q + 1] * hv.y;
            a2 += w[4 * q + 2] * hv.z;
            a3 += w[4 * q + 3] * hv.w;
        }
        float v = tanhf(((a0 + a1) + (a2 + a3)) + (x0 + b));

        x0 = x1;                          // rotate prefetch
        if (t + 2 < SEQ_LEN) x1 = g_xs[(t + 2) * HID + j];

        hs[(t & 1) ^ 1][j] = v;           // write other buffer
        g_h[t * HID + j]   = v;           // stream h history (non-blocking)
        __syncthreads();                  // single barrier per step
    }
    hfinal[j] = hs[SEQ_LEN & 1][j];
}

// ---------------------------------------------------------------------------
// Kernel 3: ys[t] = softmax(Wy h_t + Wy_b)   (parallel; warp per timestep)
// lane handles outputs j = lane, lane+32, lane+64, lane+96 (<100)
// ---------------------------------------------------------------------------
__global__ void k_out(const float* __restrict__ Wy,
                      const float* __restrict__ Wyb,
                      float* __restrict__ ys) {
    int gw   = (blockIdx.x * blockDim.x + threadIdx.x) >> 5;
    int lane = threadIdx.x & 31;
    int nw   = (gridDim.x * blockDim.x) >> 5;

    for (int t = gw; t < SEQ_LEN; t += nw) {
        // broadcast-load h_t (same addresses across the warp -> L1 broadcast)
        const float4* h4 = reinterpret_cast<const float4*>(g_h + t * HID);
        float hv[HID];
#pragma unroll
        for (int q = 0; q < HID / 4; q++) {
            float4 v = h4[q];
            hv[4 * q + 0] = v.x; hv[4 * q + 1] = v.y;
            hv[4 * q + 2] = v.z; hv[4 * q + 3] = v.w;
        }

        float lg[4];
#pragma unroll
        for (int m = 0; m < 4; m++) {
            int jj = lane + 32 * m;
            lg[m] = -1e30f;
            if (jj < IN) {
                float acc = Wyb[jj];
                const float4* w4 = reinterpret_cast<const float4*>(Wy + jj * HID);
#pragma unroll
                for (int q = 0; q < HID / 4; q++) {
                    float4 wv = w4[q];
                    acc += wv.x * hv[4 * q + 0];
                    acc += wv.y * hv[4 * q + 1];
                    acc += wv.z * hv[4 * q + 2];
                    acc += wv.w * hv[4 * q + 3];
                }
                lg[m] = acc;
            }
        }

        float mx = fmaxf(fmaxf(lg[0], lg[1]), fmaxf(lg[2], lg[3]));
#pragma unroll
        for (int o = 16; o > 0; o >>= 1)
            mx = fmaxf(mx, __shfl_xor_sync(0xffffffffu, mx, o));

        float e[4];
        float sum = 0.f;
#pragma unroll
        for (int m = 0; m < 4; m++) {
            int jj = lane + 32 * m;
            e[m] = (jj < IN) ? expf(lg[m] - mx) : 0.f;
            sum += e[m];
        }
#pragma unroll
        for (int o = 16; o > 0; o >>= 1)
            sum += __shfl_xor_sync(0xffffffffu, sum, o);

        float inv = 1.f / sum;
#pragma unroll
        for (int m = 0; m < 4; m++) {
            int jj = lane + 32 * m;
            if (jj < IN) ys[t * IN + jj] = e[m] * inv;
        }
    }
}

// ---------------------------------------------------------------------------
extern "C" void kernel_launch(void* const* d_in, const int* in_sizes, int n_in,
                              void* d_out, int out_size) {
    const float* s   = (const float*)d_in[0];
    const float* h0  = (const float*)d_in[1];
    const float* Wx  = (const float*)d_in[2];
    const float* Wxb = (const float*)d_in[3];
    const float* Wh  = (const float*)d_in[4];
    const float* Whb = (const float*)d_in[5];
    const float* Wy  = (const float*)d_in[6];
    const float* Wyb = (const float*)d_in[7];

    float* out    = (float*)d_out;
    float* hfinal = out;           // [40]
    float* ys     = out + HID;     // [SEQ_LEN, 100]

    k_xproj<<<(SEQ_LEN + 7) / 8, 320>>>(s, Wx, Wxb);
    k_recur<<<1, HID>>>(Wh, Whb, h0, hfinal);
    k_out<<<1024, 256>>>(Wy, Wyb, ys);
}

// round 2
// speedup vs baseline: 1.0334x; 1.0334x over previous
#include <cuda_runtime.h>

#define SEQ_LEN 131072
#define IN 100
#define HID 40
#define TILE 128                      // timesteps per consumer tile
#define NT (SEQ_LEN / TILE)           // 1024 tiles

typedef unsigned long long u64;

// Scratch: device globals (no allocations allowed)
__device__ float g_xs[(SEQ_LEN + 2) * HID];   // input projections (+2 pad rows for prefetch)
__device__ float g_h[SEQ_LEN * HID];          // hidden states per step
__device__ unsigned g_progress;               // steps completed (reset via memsetAsync)

// ---- packed f32x2 helpers (sm_103a) ---------------------------------------
__device__ __forceinline__ u64 ffma2(u64 a, u64 b, u64 c) {
    u64 d; asm("fma.rn.f32x2 %0, %1, %2, %3;" : "=l"(d) : "l"(a), "l"(b), "l"(c));
    return d;
}
__device__ __forceinline__ u64 fadd2(u64 a, u64 b) {
    u64 d; asm("add.rn.f32x2 %0, %1, %2;" : "=l"(d) : "l"(a), "l"(b));
    return d;
}
__device__ __forceinline__ float hsum2(u64 a) {
    unsigned lo, hi; asm("mov.b64 {%0, %1}, %2;" : "=r"(lo), "=r"(hi) : "l"(a));
    return __uint_as_float(lo) + __uint_as_float(hi);
}
__device__ __forceinline__ void st_release(unsigned* p, unsigned v) {
    asm volatile("st.release.gpu.u32 [%0], %1;" :: "l"(p), "r"(v) : "memory");
}
__device__ __forceinline__ unsigned ld_acquire(const unsigned* p) {
    unsigned v; asm volatile("ld.acquire.gpu.u32 %0, [%1];" : "=r"(v) : "l"(p) : "memory");
    return v;
}
// branchless fast tanh: 1 - 2/(exp(2x)+1); saturates correctly at +/-inf
__device__ __forceinline__ float fast_tanh(float x) {
    float e = __expf(2.0f * x);
    return 1.0f - __fdividef(2.0f, e + 1.0f);
}

// ---------------------------------------------------------------------------
// Kernel 1: xs[t] = Wx @ s[t] + Wx_b   (parallel over t)
// ---------------------------------------------------------------------------
__global__ void k_xproj(const float* __restrict__ s,
                        const float* __restrict__ Wx,
                        const float* __restrict__ Wxb) {
    __shared__ float sWx[HID][IN + 1];
    __shared__ float sb[HID];
    for (int i = threadIdx.x; i < HID * IN; i += blockDim.x)
        sWx[i / IN][i % IN] = Wx[i];
    if (threadIdx.x < HID) sb[threadIdx.x] = Wxb[threadIdx.x];
    __syncthreads();

    int lt = threadIdx.x / HID;
    int j  = threadIdx.x % HID;
    int t  = blockIdx.x * 8 + lt;
    if (t >= SEQ_LEN) return;

    const float4* s4 = reinterpret_cast<const float4*>(s + t * IN);
    float acc = sb[j];
#pragma unroll
    for (int q = 0; q < IN / 4; q++) {
        float4 v = s4[q];
        acc += v.x * sWx[j][4 * q + 0];
        acc += v.y * sWx[j][4 * q + 1];
        acc += v.z * sWx[j][4 * q + 2];
        acc += v.w * sWx[j][4 * q + 3];
    }
    g_xs[t * HID + j] = acc;
}

// ---------------------------------------------------------------------------
// Kernel 2 (fused): block 0 = sequential recurrence producer (40 threads);
// blocks 1..147 = softmax consumers polling the progress flag.
// ---------------------------------------------------------------------------
__global__ void __launch_bounds__(256, 1)
k_fused(const float* __restrict__ Wh,  const float* __restrict__ Whb,
        const float* __restrict__ h0,
        const float* __restrict__ Wy,  const float* __restrict__ Wyb,
        float* __restrict__ hfinal,    float* __restrict__ ys) {

    if (blockIdx.x == 0) {
        // ================= producer: recurrence ===========================
        int j = threadIdx.x;
        if (j >= HID) return;                 // exited threads don't count in bar

        __shared__ __align__(16) float hs[2][HID];

        // Wh row j pre-packed into 20 f32x2 registers
        u64 w[HID / 2];
        const longlong2* wrow = reinterpret_cast<const longlong2*>(Wh + j * HID);
#pragma unroll
        for (int q = 0; q < HID / 8 * 2; q++) {   // 10 iters
            longlong2 v = wrow[q];
            w[2 * q]     = (u64)v.x;
            w[2 * q + 1] = (u64)v.y;
        }
        float b = Whb[j];

        hs[0][j] = h0[j];
        __syncthreads();

        float c  = g_xs[j] + b;               // xs[0][j] + b
        float xn = g_xs[HID + j];             // xs[1][j]
        float v  = 0.f;

        for (int t = 0; t < SEQ_LEN; t++) {
            const longlong2* hc = reinterpret_cast<const longlong2*>(hs[t & 1]);
            u64 a0 = 0ull, a1 = 0ull, a2 = 0ull, a3 = 0ull;
#pragma unroll
            for (int q = 0; q < 10; q += 2) {
                longlong2 h01 = hc[q];
                longlong2 h23 = hc[q + 1];
                a0 = ffma2(w[2 * q],     (u64)h01.x, a0);
                a1 = ffma2(w[2 * q + 1], (u64)h01.y, a1);
                a2 = ffma2(w[2 * q + 2], (u64)h23.x, a2);
                a3 = ffma2(w[2 * q + 3], (u64)h23.y, a3);
            }
            float z = hsum2(fadd2(fadd2(a0, a1), fadd2(a2, a3))) + c;
            v = fast_tanh(z);

            c  = xn + b;                      // rotate prefetch (padded, no branch)
            xn = g_xs[(t + 2) * HID + j];

            hs[(t & 1) ^ 1][j] = v;
            g_h[t * HID + j]   = v;
            __syncthreads();

            if ((t & (TILE - 1)) == (TILE - 1) && j == 0)
                st_release(&g_progress, (unsigned)(t + 1));
        }
        hfinal[j] = v;
    } else {
        // ================= consumers: per-step softmax ====================
        __shared__ unsigned ready;
        int lane = threadIdx.x & 31;
        int wrp  = threadIdx.x >> 5;          // 0..7

        for (int tile = blockIdx.x - 1; tile < NT; tile += (int)gridDim.x - 1) {
            unsigned need = (unsigned)((tile + 1) * TILE);
            if (threadIdx.x == 0) {
                unsigned p = ld_acquire(&g_progress);
                while (p < need) { __nanosleep(256); p = ld_acquire(&g_progress); }
                ready = p;
            }
            __syncthreads();

            int base = tile * TILE;
            for (int k = 0; k < TILE / 8; k++) {
                int t = base + wrp + 8 * k;

                const float4* h4 = reinterpret_cast<const float4*>(g_h + t * HID);
                float hv[HID];
#pragma unroll
                for (int q = 0; q < HID / 4; q++) {
                    float4 vv = h4[q];
                    hv[4 * q + 0] = vv.x; hv[4 * q + 1] = vv.y;
                    hv[4 * q + 2] = vv.z; hv[4 * q + 3] = vv.w;
                }

                float lg[4];
#pragma unroll
                for (int m = 0; m < 4; m++) {
                    int jj = lane + 32 * m;
                    lg[m] = -1e30f;
                    if (jj < IN) {
                        float acc = Wyb[jj];
                        const float4* w4 = reinterpret_cast<const float4*>(Wy + jj * HID);
#pragma unroll
                        for (int q = 0; q < HID / 4; q++) {
                            float4 wv = w4[q];
                            acc += wv.x * hv[4 * q + 0];
                            acc += wv.y * hv[4 * q + 1];
                            acc += wv.z * hv[4 * q + 2];
                            acc += wv.w * hv[4 * q + 3];
                        }
                        lg[m] = acc;
                    }
                }

                float mx = fmaxf(fmaxf(lg[0], lg[1]), fmaxf(lg[2], lg[3]));
#pragma unroll
                for (int o = 16; o > 0; o >>= 1)
                    mx = fmaxf(mx, __shfl_xor_sync(0xffffffffu, mx, o));

                float e[4];
                float sum = 0.f;
#pragma unroll
                for (int m = 0; m < 4; m++) {
                    int jj = lane + 32 * m;
                    e[m] = (jj < IN) ? __expf(lg[m] - mx) : 0.f;
                    sum += e[m];
                }
#pragma unroll
                for (int o = 16; o > 0; o >>= 1)
                    sum += __shfl_xor_sync(0xffffffffu, sum, o);

                float inv = __frcp_rn(sum);
#pragma unroll
                for (int m = 0; m < 4; m++) {
                    int jj = lane + 32 * m;
                    if (jj < IN) ys[t * IN + jj] = e[m] * inv;
                }
            }
        }
    }
}

// ---------------------------------------------------------------------------
extern "C" void kernel_launch(void* const* d_in, const int* in_sizes, int n_in,
                              void* d_out, int out_size) {
    const float* s   = (const float*)d_in[0];
    const float* h0  = (const float*)d_in[1];
    const float* Wx  = (const float*)d_in[2];
    const float* Wxb = (const float*)d_in[3];
    const float* Wh  = (const float*)d_in[4];
    const float* Whb = (const float*)d_in[5];
    const float* Wy  = (const float*)d_in[6];
    const float* Wyb = (const float*)d_in[7];

    float* out    = (float*)d_out;
    float* hfinal = out;           // [40]
    float* ys     = out + HID;     // [SEQ_LEN, 100]

    // reset progress flag each replay (async memset: graph-capturable, no alloc)
    void* pprog = nullptr;
    cudaGetSymbolAddress(&pprog, g_progress);
    cudaMemsetAsync(pprog, 0, sizeof(unsigned));

    k_xproj<<<(SEQ_LEN + 7) / 8, 320>>>(s, Wx, Wxb);
    k_fused<<<148, 256>>>(Wh, Whb, h0, Wy, Wyb, hfinal, ys);
}

// round 3
// speedup vs baseline: 1.8062x; 1.7479x over previous
#include <cuda_runtime.h>

#define SEQ_LEN 131072
#define IN 100
#define HID 40
#define TILE 128                      // timesteps per consumer tile
#define NT (SEQ_LEN / TILE)           // 1024 tiles
#define PF 8                          // xs prefetch depth (ring in registers)

typedef unsigned long long u64;

// Scratch: device globals (no allocations allowed)
__device__ float g_xs[(SEQ_LEN + PF) * HID];  // input projections (+PF pad rows)
__device__ float g_h[SEQ_LEN * HID];          // hidden states per step
__device__ unsigned g_progress;               // steps completed (reset via memsetAsync)

// ---- packed f32x2 helpers (sm_103a) ---------------------------------------
__device__ __forceinline__ u64 ffma2(u64 a, u64 b, u64 c) {
    u64 d; asm("fma.rn.f32x2 %0, %1, %2, %3;" : "=l"(d) : "l"(a), "l"(b), "l"(c));
    return d;
}
__device__ __forceinline__ u64 fadd2(u64 a, u64 b) {
    u64 d; asm("add.rn.f32x2 %0, %1, %2;" : "=l"(d) : "l"(a), "l"(b));
    return d;
}
__device__ __forceinline__ float hsum2(u64 a) {
    unsigned lo, hi; asm("mov.b64 {%0, %1}, %2;" : "=r"(lo), "=r"(hi) : "l"(a));
    return __uint_as_float(lo) + __uint_as_float(hi);
}
__device__ __forceinline__ void st_release(unsigned* p, unsigned v) {
    asm volatile("st.release.gpu.u32 [%0], %1;" :: "l"(p), "r"(v) : "memory");
}
__device__ __forceinline__ unsigned ld_acquire(const unsigned* p) {
    unsigned v; asm volatile("ld.acquire.gpu.u32 %0, [%1];" : "=r"(v) : "l"(p) : "memory");
    return v;
}
__device__ __forceinline__ float mufu_tanh(float x) {
    float r; asm("tanh.approx.f32 %0, %1;" : "=f"(r) : "f"(x));
    return r;
}

// ---------------------------------------------------------------------------
// Kernel 1: xs[t] = Wx @ s[t] + Wx_b   (parallel over t)
// ---------------------------------------------------------------------------
__global__ void k_xproj(const float* __restrict__ s,
                        const float* __restrict__ Wx,
                        const float* __restrict__ Wxb) {
    __shared__ float sWx[HID][IN + 1];
    __shared__ float sb[HID];
    for (int i = threadIdx.x; i < HID * IN; i += blockDim.x)
        sWx[i / IN][i % IN] = Wx[i];
    if (threadIdx.x < HID) sb[threadIdx.x] = Wxb[threadIdx.x];
    __syncthreads();

    int lt = threadIdx.x / HID;
    int j  = threadIdx.x % HID;
    int t  = blockIdx.x * 8 + lt;
    if (t >= SEQ_LEN) return;

    const float4* s4 = reinterpret_cast<const float4*>(s + t * IN);
    float acc = sb[j];
#pragma unroll
    for (int q = 0; q < IN / 4; q++) {
        float4 v = s4[q];
        acc += v.x * sWx[j][4 * q + 0];
        acc += v.y * sWx[j][4 * q + 1];
        acc += v.z * sWx[j][4 * q + 2];
        acc += v.w * sWx[j][4 * q + 3];
    }
    g_xs[t * HID + j] = acc;
}

// ---------------------------------------------------------------------------
// Kernel 2 (fused): block 0 = sequential recurrence producer (40 threads);
// blocks 1..147 = softmax consumers polling the progress flag.
// ---------------------------------------------------------------------------
__global__ void __launch_bounds__(256, 1)
k_fused(const float* __restrict__ Wh,  const float* __restrict__ Whb,
        const float* __restrict__ h0,
        const float* __restrict__ Wy,  const float* __restrict__ Wyb,
        float* __restrict__ hfinal,    float* __restrict__ ys) {

    if (blockIdx.x == 0) {
        // ================= producer: recurrence ===========================
        int j = threadIdx.x;
        if (j >= HID) return;                 // exited threads don't count in bar

        __shared__ __align__(16) float hs[2][HID];

        // Wh row j pre-packed into 20 f32x2 registers
        u64 w[HID / 2];
        const longlong2* wrow = reinterpret_cast<const longlong2*>(Wh + j * HID);
#pragma unroll
        for (int q = 0; q < HID / 4; q++) {   // 10 iters
            longlong2 v = wrow[q];
            w[2 * q]     = (u64)v.x;
            w[2 * q + 1] = (u64)v.y;
        }
        float b = Whb[j];

        hs[0][j] = h0[j];
        __syncthreads();

        // deep prefetch ring: xf[k] holds xs[t] for t ≡ k (mod PF)
        float xf[PF];
#pragma unroll
        for (int k = 0; k < PF; k++) xf[k] = g_xs[k * HID + j];

        float v = 0.f;

        for (int tb = 0; tb < SEQ_LEN; tb += PF) {
#pragma unroll
            for (int k = 0; k < PF; k++) {
                const int t = tb + k;                 // t&1 == k&1 (PF even)
                const longlong2* hc = reinterpret_cast<const longlong2*>(hs[k & 1]);
                u64 a0 = 0ull, a1 = 0ull, a2 = 0ull, a3 = 0ull;
#pragma unroll
                for (int q = 0; q < 10; q += 2) {
                    longlong2 h01 = hc[q];
                    longlong2 h23 = hc[q + 1];
                    a0 = ffma2(w[2 * q],     (u64)h01.x, a0);
                    a1 = ffma2(w[2 * q + 1], (u64)h01.y, a1);
                    a2 = ffma2(w[2 * q + 2], (u64)h23.x, a2);
                    a3 = ffma2(w[2 * q + 3], (u64)h23.y, a3);
                }
                float z = hsum2(fadd2(fadd2(a0, a1), fadd2(a2, a3))) + (xf[k] + b);
                v = mufu_tanh(z);

                xf[k] = g_xs[(tb + k + PF) * HID + j];   // refill slot (padded)

                hs[(k & 1) ^ 1][j] = v;
                g_h[t * HID + j]   = v;
                __syncthreads();

                if (k == PF - 1 && (tb & (TILE - 1)) == (TILE - PF) && j == 0)
                    st_release(&g_progress, (unsigned)(t + 1));
            }
        }
        hfinal[j] = v;
    } else {
        // ================= consumers: per-step softmax ====================
        __shared__ unsigned ready;
        int lane = threadIdx.x & 31;
        int wrp  = threadIdx.x >> 5;          // 0..7

        for (int tile = blockIdx.x - 1; tile < NT; tile += (int)gridDim.x - 1) {
            unsigned need = (unsigned)((tile + 1) * TILE);
            if (threadIdx.x == 0) {
                unsigned p = ld_acquire(&g_progress);
                while (p < need) { __nanosleep(256); p = ld_acquire(&g_progress); }
                ready = p;
            }
            __syncthreads();

            int base = tile * TILE;
            for (int k = 0; k < TILE / 8; k++) {
                int t = base + wrp + 8 * k;

                const float4* h4 = reinterpret_cast<const float4*>(g_h + t * HID);
                float hv[HID];
#pragma unroll
                for (int q = 0; q < HID / 4; q++) {
                    float4 vv = h4[q];
                    hv[4 * q + 0] = vv.x; hv[4 * q + 1] = vv.y;
                    hv[4 * q + 2] = vv.z; hv[4 * q + 3] = vv.w;
                }

                float lg[4];
#pragma unroll
                for (int m = 0; m < 4; m++) {
                    int jj = lane + 32 * m;
                    lg[m] = -1e30f;
                    if (jj < IN) {
                        float acc = Wyb[jj];
                        const float4* w4 = reinterpret_cast<const float4*>(Wy + jj * HID);
#pragma unroll
                        for (int q = 0; q < HID / 4; q++) {
                            float4 wv = w4[q];
                            acc += wv.x * hv[4 * q + 0];
                            acc += wv.y * hv[4 * q + 1];
                            acc += wv.z * hv[4 * q + 2];
                            acc += wv.w * hv[4 * q + 3];
                        }
                        lg[m] = acc;
                    }
                }

                float mx = fmaxf(fmaxf(lg[0], lg[1]), fmaxf(lg[2], lg[3]));
#pragma unroll
                for (int o = 16; o > 0; o >>= 1)
                    mx = fmaxf(mx, __shfl_xor_sync(0xffffffffu, mx, o));

                float e[4];
                float sum = 0.f;
#pragma unroll
                for (int m = 0; m < 4; m++) {
                    int jj = lane + 32 * m;
                    e[m] = (jj < IN) ? __expf(lg[m] - mx) : 0.f;
                    sum += e[m];
                }
#pragma unroll
                for (int o = 16; o > 0; o >>= 1)
                    sum += __shfl_xor_sync(0xffffffffu, sum, o);

                float inv = __frcp_rn(sum);
#pragma unroll
                for (int m = 0; m < 4; m++) {
                    int jj = lane + 32 * m;
                    if (jj < IN) ys[t * IN + jj] = e[m] * inv;
                }
            }
        }
    }
}

// ---------------------------------------------------------------------------
extern "C" void kernel_launch(void* const* d_in, const int* in_sizes, int n_in,
                              void* d_out, int out_size) {
    const float* s   = (const float*)d_in[0];
    const float* h0  = (const float*)d_in[1];
    const float* Wx  = (const float*)d_in[2];
    const float* Wxb = (const float*)d_in[3];
    const float* Wh  = (const float*)d_in[4];
    const float* Whb = (const float*)d_in[5];
    const float* Wy  = (const float*)d_in[6];
    const float* Wyb = (const float*)d_in[7];

    float* out    = (float*)d_out;
    float* hfinal = out;           // [40]
    float* ys     = out + HID;     // [SEQ_LEN, 100]

    // reset progress flag each replay (async memset: graph-capturable, no alloc)
    void* pprog = nullptr;
    cudaGetSymbolAddress(&pprog, g_progress);
    cudaMemsetAsync(pprog, 0, sizeof(unsigned));

    k_xproj<<<(SEQ_LEN + 7) / 8, 320>>>(s, Wx, Wxb);
    k_fused<<<148, 256>>>(Wh, Whb, h0, Wy, Wyb, hfinal, ys);
}